// round 1
// baseline (speedup 1.0000x reference)
#include <cuda_runtime.h>
#include <math.h>

// Problem constants
#define BB 4
#define SS 2048
#define EE 1024

// Scratch: q, k, v projections (32 MB each) + scores (64 MB)
__device__ float g_q[(size_t)BB * SS * EE];
__device__ float g_k[(size_t)BB * SS * EE];
__device__ float g_v[(size_t)BB * SS * EE];
__device__ float g_sc[(size_t)BB * SS * SS];

// ---------------------------------------------------------------------------
// Tiled fp32 GEMM, BM=BN=128, BK=16, 256 threads, 8x8 per thread.
// ---------------------------------------------------------------------------
constexpr int BM = 128, BN = 128, BK = 16, TM = 8, TN = 8;

// C = alpha * (A @ B^T) + bias ; A:[M,K] row-major, Bm:[N,K] row-major.
// CAUSAL_SKIP: skip tiles strictly above the block diagonal (bx > by).
template <bool CAUSAL_SKIP>
__global__ __launch_bounds__(256)
void gemm_nt_kernel(const float* __restrict__ A, const float* __restrict__ Bm,
                    const float* __restrict__ bias, float* __restrict__ C,
                    int M, int N, int K, float alpha,
                    size_t sA, size_t sB, size_t sC)
{
    if (CAUSAL_SKIP && blockIdx.x > blockIdx.y) return;
    A  += (size_t)blockIdx.z * sA;
    Bm += (size_t)blockIdx.z * sB;
    C  += (size_t)blockIdx.z * sC;

    __shared__ float As[BK][BM + 4];
    __shared__ float Bs[BK][BN + 4];

    const int t  = threadIdx.x;
    const int tx = t % 16;          // col group
    const int ty = t / 16;          // row group
    const int rowBase = blockIdx.y * BM;
    const int colBase = blockIdx.x * BN;

    float acc[TM][TN] = {};

    for (int kt = 0; kt < K; kt += BK) {
        // Load A tile (128 rows x 16 k), transposed into As[k][row]
        #pragma unroll
        for (int it = 0; it < 2; it++) {
            int r = t / 4 + it * 64;
            int k = (t % 4) * 4;
            float4 va = *(const float4*)&A[(size_t)(rowBase + r) * K + kt + k];
            As[k + 0][r] = va.x; As[k + 1][r] = va.y;
            As[k + 2][r] = va.z; As[k + 3][r] = va.w;
        }
        // Load B tile (128 n-rows x 16 k), transposed into Bs[k][col]
        #pragma unroll
        for (int it = 0; it < 2; it++) {
            int r = t / 4 + it * 64;
            int k = (t % 4) * 4;
            float4 vb = *(const float4*)&Bm[(size_t)(colBase + r) * K + kt + k];
            Bs[k + 0][r] = vb.x; Bs[k + 1][r] = vb.y;
            Bs[k + 2][r] = vb.z; Bs[k + 3][r] = vb.w;
        }
        __syncthreads();

        #pragma unroll
        for (int kk = 0; kk < BK; kk++) {
            float a[TM], b[TN];
            *(float4*)&a[0] = *(const float4*)&As[kk][ty * TM];
            *(float4*)&a[4] = *(const float4*)&As[kk][ty * TM + 4];
            *(float4*)&b[0] = *(const float4*)&Bs[kk][tx * TN];
            *(float4*)&b[4] = *(const float4*)&Bs[kk][tx * TN + 4];
            #pragma unroll
            for (int i = 0; i < TM; i++)
                #pragma unroll
                for (int j = 0; j < TN; j++)
                    acc[i][j] = fmaf(a[i], b[j], acc[i][j]);
        }
        __syncthreads();
    }

    // Epilogue
    float bb[TN];
    #pragma unroll
    for (int j = 0; j < TN; j++)
        bb[j] = bias ? bias[colBase + tx * TN + j] : 0.0f;

    #pragma unroll
    for (int i = 0; i < TM; i++) {
        size_t off = (size_t)(rowBase + ty * TM + i) * N + colBase + tx * TN;
        #pragma unroll
        for (int jv = 0; jv < TN; jv += 4) {
            float4 o;
            o.x = alpha * acc[i][jv + 0] + bb[jv + 0];
            o.y = alpha * acc[i][jv + 1] + bb[jv + 1];
            o.z = alpha * acc[i][jv + 2] + bb[jv + 2];
            o.w = alpha * acc[i][jv + 3] + bb[jv + 3];
            *(float4*)&C[off + jv] = o;
        }
    }
}

// C = alpha * (A @ B) ; A:[M,K] row-major, B:[K,N] row-major.
// K_LIMIT: causal — rows in block by only need k < (by+1)*BM (attn tail is 0).
template <bool K_LIMIT>
__global__ __launch_bounds__(256)
void gemm_nn_kernel(const float* __restrict__ A, const float* __restrict__ Bm,
                    float* __restrict__ C,
                    int M, int N, int K, float alpha,
                    size_t sA, size_t sB, size_t sC)
{
    A  += (size_t)blockIdx.z * sA;
    Bm += (size_t)blockIdx.z * sB;
    C  += (size_t)blockIdx.z * sC;

    __shared__ float As[BK][BM + 4];
    __shared__ float Bs[BK][BN + 4];

    const int t  = threadIdx.x;
    const int tx = t % 16;
    const int ty = t / 16;
    const int rowBase = blockIdx.y * BM;
    const int colBase = blockIdx.x * BN;

    const int kEnd = K_LIMIT ? min(K, (int)(blockIdx.y + 1) * BM) : K;

    float acc[TM][TN] = {};

    for (int kt = 0; kt < kEnd; kt += BK) {
        // Load A tile transposed
        #pragma unroll
        for (int it = 0; it < 2; it++) {
            int r = t / 4 + it * 64;
            int k = (t % 4) * 4;
            float4 va = *(const float4*)&A[(size_t)(rowBase + r) * K + kt + k];
            As[k + 0][r] = va.x; As[k + 1][r] = va.y;
            As[k + 2][r] = va.z; As[k + 3][r] = va.w;
        }
        // Load B tile: B[k][n] direct (n contiguous) -> Bs[k][col]
        #pragma unroll
        for (int it = 0; it < 2; it++) {
            int kk = t / 32 + it * 8;
            int c  = (t % 32) * 4;
            float4 vb = *(const float4*)&Bm[(size_t)(kt + kk) * N + colBase + c];
            *(float4*)&Bs[kk][c] = vb;
        }
        __syncthreads();

        #pragma unroll
        for (int kk = 0; kk < BK; kk++) {
            float a[TM], b[TN];
            *(float4*)&a[0] = *(const float4*)&As[kk][ty * TM];
            *(float4*)&a[4] = *(const float4*)&As[kk][ty * TM + 4];
            *(float4*)&b[0] = *(const float4*)&Bs[kk][tx * TN];
            *(float4*)&b[4] = *(const float4*)&Bs[kk][tx * TN + 4];
            #pragma unroll
            for (int i = 0; i < TM; i++)
                #pragma unroll
                for (int j = 0; j < TN; j++)
                    acc[i][j] = fmaf(a[i], b[j], acc[i][j]);
        }
        __syncthreads();
    }

    #pragma unroll
    for (int i = 0; i < TM; i++) {
        size_t off = (size_t)(rowBase + ty * TM + i) * N + colBase + tx * TN;
        #pragma unroll
        for (int jv = 0; jv < TN; jv += 4) {
            float4 o;
            o.x = alpha * acc[i][jv + 0];
            o.y = alpha * acc[i][jv + 1];
            o.z = alpha * acc[i][jv + 2];
            o.w = alpha * acc[i][jv + 3];
            *(float4*)&C[off + jv] = o;
        }
    }
}

// ---------------------------------------------------------------------------
// Causal row softmax, in place on scores. One 256-thread block per row.
// Also zeroes [L, kend) so the AV GEMM can run whole 128-wide K-blocks.
// ---------------------------------------------------------------------------
__global__ void softmax_kernel(float* __restrict__ sc)
{
    const int row = blockIdx.x;           // 0 .. B*S-1
    const int b = row >> 11;              // /2048
    const int i = row & (SS - 1);
    float* p = sc + (size_t)b * SS * SS + (size_t)i * SS;
    const int L = i + 1;
    const int kend = ((i >> 7) + 1) << 7; // next multiple of 128

    __shared__ float red[8];
    __shared__ float red2[8];
    const int t = threadIdx.x;
    const int lane = t & 31, w = t >> 5;

    // 1) max
    float m = -1e30f;
    for (int j = t; j < L; j += 256) m = fmaxf(m, p[j]);
    #pragma unroll
    for (int o = 16; o; o >>= 1) m = fmaxf(m, __shfl_xor_sync(~0u, m, o));
    if (lane == 0) red[w] = m;
    __syncthreads();
    m = red[0];
    #pragma unroll
    for (int ww = 1; ww < 8; ww++) m = fmaxf(m, red[ww]);

    // 2) exp + sum
    float s = 0.0f;
    for (int j = t; j < L; j += 256) {
        float e = __expf(p[j] - m);
        p[j] = e;
        s += e;
    }
    #pragma unroll
    for (int o = 16; o; o >>= 1) s += __shfl_xor_sync(~0u, s, o);
    if (lane == 0) red2[w] = s;
    __syncthreads();
    s = red2[0];
    #pragma unroll
    for (int ww = 1; ww < 8; ww++) s += red2[ww];

    // 3) normalize + zero causal tail up to 128-block boundary
    float inv = 1.0f / s;
    for (int j = t; j < L; j += 256) p[j] *= inv;
    for (int j = L + t; j < kend; j += 256) p[j] = 0.0f;
}

// ---------------------------------------------------------------------------
// Launch
// ---------------------------------------------------------------------------
extern "C" void kernel_launch(void* const* d_in, const int* in_sizes, int n_in,
                              void* d_out, int out_size)
{
    const float* x  = (const float*)d_in[0];
    // d_in[1] = masked (always 1 in this problem)
    const float* Wq = (const float*)d_in[2];
    const float* bq = (const float*)d_in[3];
    const float* Wk = (const float*)d_in[4];
    const float* bk = (const float*)d_in[5];
    const float* Wv = (const float*)d_in[6];
    const float* bv = (const float*)d_in[7];
    float* out = (float*)d_out;

    float *q, *k, *v, *sc;
    cudaGetSymbolAddress((void**)&q,  g_q);
    cudaGetSymbolAddress((void**)&k,  g_k);
    cudaGetSymbolAddress((void**)&v,  g_v);
    cudaGetSymbolAddress((void**)&sc, g_sc);

    dim3 blk(256);

    // QKV projections: y = x @ W^T + b   (M=8192, N=1024, K=1024)
    dim3 g1(EE / BN, (BB * SS) / BM);
    gemm_nt_kernel<false><<<g1, blk>>>(x, Wq, bq, q, BB * SS, EE, EE, 1.0f, 0, 0, 0);
    gemm_nt_kernel<false><<<g1, blk>>>(x, Wk, bk, k, BB * SS, EE, EE, 1.0f, 0, 0, 0);
    gemm_nt_kernel<false><<<g1, blk>>>(x, Wv, bv, v, BB * SS, EE, EE, 1.0f, 0, 0, 0);

    // Scores: sc = (q @ k^T) / 32, lower-triangular blocks only
    dim3 g2(SS / BN, SS / BM, BB);
    gemm_nt_kernel<true><<<g2, blk>>>(q, k, nullptr, sc, SS, SS, EE, 0.03125f,
                                      (size_t)SS * EE, (size_t)SS * EE, (size_t)SS * SS);

    // Causal softmax rows
    softmax_kernel<<<BB * SS, 256>>>(sc);

    // Output: out = attn @ v, with causal K limit
    dim3 g3(EE / BN, SS / BM, BB);
    gemm_nn_kernel<true><<<g3, blk>>>(sc, v, out, SS, EE, SS, 1.0f,
                                      (size_t)SS * SS, (size_t)SS * EE, (size_t)SS * EE);
}

// round 3
// speedup vs baseline: 1.9741x; 1.9741x over previous
#include <cuda_runtime.h>
#include <cuda_bf16.h>

#define BB 4
#define SS 2048
#define EE 1024

typedef __nv_bfloat16 bf16;

// ---------------------------------------------------------------------------
// Scratch (device globals — no allocation allowed)
// ---------------------------------------------------------------------------
__device__ float g_sc[(size_t)BB * SS * SS];
__device__ bf16 g_xh[(size_t)BB * SS * EE], g_xl[(size_t)BB * SS * EE];
__device__ bf16 g_Wh[3 * (size_t)EE * EE], g_Wl[3 * (size_t)EE * EE];
__device__ bf16 g_qh[(size_t)BB * SS * EE], g_ql[(size_t)BB * SS * EE];
__device__ bf16 g_kh[(size_t)BB * SS * EE], g_kl[(size_t)BB * SS * EE];
__device__ bf16 g_vh[(size_t)BB * SS * EE], g_vl[(size_t)BB * SS * EE];
__device__ bf16 g_vTh[(size_t)BB * EE * SS], g_vTl[(size_t)BB * EE * SS];
__device__ bf16 g_ph[(size_t)BB * SS * SS], g_pl[(size_t)BB * SS * SS];

// ---------------------------------------------------------------------------
// PTX helpers (all baseline sm_80+ features: valid for plain sm_103 target)
// ---------------------------------------------------------------------------
__device__ __forceinline__ unsigned smem_u32(const void* p) {
    unsigned a;
    asm("{ .reg .u64 t; cvta.to.shared.u64 t, %1; cvt.u32.u64 %0, t; }"
        : "=r"(a) : "l"(p));
    return a;
}
__device__ __forceinline__ void cp16(unsigned dst, const void* src) {
    asm volatile("cp.async.cg.shared.global [%0], [%1], 16;"
                 :: "r"(dst), "l"(src) : "memory");
}
__device__ __forceinline__ void cp_commit() {
    asm volatile("cp.async.commit_group;" ::: "memory");
}
__device__ __forceinline__ void cp_wait1() {
    asm volatile("cp.async.wait_group 1;" ::: "memory");
}
__device__ __forceinline__ void cp_wait0() {
    asm volatile("cp.async.wait_group 0;" ::: "memory");
}
__device__ __forceinline__ void ldsm4(unsigned& r0, unsigned& r1, unsigned& r2,
                                      unsigned& r3, unsigned addr) {
    asm volatile("ldmatrix.sync.aligned.m8n8.x4.shared.b16 {%0,%1,%2,%3}, [%4];"
                 : "=r"(r0), "=r"(r1), "=r"(r2), "=r"(r3) : "r"(addr));
}
__device__ __forceinline__ void mma16816(float* d, const unsigned* a,
                                         unsigned b0, unsigned b1) {
    asm volatile(
        "mma.sync.aligned.m16n8k16.row.col.f32.bf16.bf16.f32 "
        "{%0,%1,%2,%3}, {%4,%5,%6,%7}, {%8,%9}, {%0,%1,%2,%3};"
        : "+f"(d[0]), "+f"(d[1]), "+f"(d[2]), "+f"(d[3])
        : "r"(a[0]), "r"(a[1]), "r"(a[2]), "r"(a[3]), "r"(b0), "r"(b1));
}

// ---------------------------------------------------------------------------
// GEMM core: C(128x128 fp32 regs) = sum of 3 passes of A @ B^T
// A: [M,K] bf16 row-major (lda), B: [N,K] bf16 row-major (ldb)
// 256 threads; warp grid 4(M) x 2(N); each warp 32x64.
// Smem: [buf][A/B][128 rows][40 cols bf16] (80B padded rows)
// ---------------------------------------------------------------------------
#define ROWPAD 40

struct SmemGemm {
    bf16 t[2][2][128][ROWPAD];
};

__device__ __forceinline__ void load_tiles(
    SmemGemm* sm, int buf, const bf16* As, const bf16* Bs,
    int lda, int ldb, int rowBase, int colBase, int kt, int tid)
{
    const char* gA = (const char*)(As + (size_t)rowBase * lda + kt);
    const char* gB = (const char*)(Bs + (size_t)colBase * ldb + kt);
    const size_t strA = (size_t)lda * 2, strB = (size_t)ldb * 2;
    unsigned sA = smem_u32(&sm->t[buf][0][0][0]);
    unsigned sB = smem_u32(&sm->t[buf][1][0][0]);
    #pragma unroll
    for (int i = 0; i < 2; i++) {
        int idx = tid + i * 256;
        int row = idx >> 2, c = (idx & 3) * 16;
        cp16(sA + row * (ROWPAD * 2) + c, gA + row * strA + c);
        cp16(sB + row * (ROWPAD * 2) + c, gB + row * strB + c);
    }
}

__device__ __forceinline__ void gemm_mainloop(
    const bf16* __restrict__ Ah, const bf16* __restrict__ Al, int lda,
    const bf16* __restrict__ Bh, const bf16* __restrict__ Bl, int ldb,
    int kEnd, int rowBase, int colBase, SmemGemm* sm,
    float acc[2][8][4])
{
    const int tid = threadIdx.x;
    const int lane = tid & 31, wid = tid >> 5;
    const int wm = wid & 3, wn = wid >> 2;     // warp 32(M) x 64(N)
    const int kTiles = kEnd >> 5;
    const int iters = 3 * kTiles;

    // per-lane ldmatrix address components
    const int lrow = lane & 15;                 // row within 16
    const int lk = (lane >> 4) * 16;            // 16B k-half offset (bytes)

    load_tiles(sm, 0, Ah, Bh, lda, ldb, rowBase, colBase, 0, tid);
    cp_commit();

    for (int it = 0; it < iters; ++it) {
        if (it + 1 < iters) {
            int pass = (it + 1) / kTiles;
            int kt = ((it + 1) - pass * kTiles) << 5;
            const bf16* As = (pass == 1) ? Al : Ah;
            const bf16* Bs = (pass == 2) ? Bl : Bh;
            load_tiles(sm, (it + 1) & 1, As, Bs, lda, ldb, rowBase, colBase, kt, tid);
            cp_commit();
            cp_wait1();
        } else {
            cp_wait0();
        }
        __syncthreads();

        int buf = it & 1;
        unsigned baseA = smem_u32(&sm->t[buf][0][0][0]);
        unsigned baseB = smem_u32(&sm->t[buf][1][0][0]);

        #pragma unroll
        for (int ks = 0; ks < 2; ks++) {
            unsigned a[2][4];
            #pragma unroll
            for (int mi = 0; mi < 2; mi++) {
                int row = wm * 32 + mi * 16 + lrow;
                ldsm4(a[mi][0], a[mi][1], a[mi][2], a[mi][3],
                      baseA + row * (ROWPAD * 2) + ks * 32 + lk);
            }
            unsigned bfr[4][4];
            #pragma unroll
            for (int nj = 0; nj < 4; nj++) {
                int row = wn * 64 + nj * 16 + lrow;
                ldsm4(bfr[nj][0], bfr[nj][1], bfr[nj][2], bfr[nj][3],
                      baseB + row * (ROWPAD * 2) + ks * 32 + lk);
            }
            #pragma unroll
            for (int mi = 0; mi < 2; mi++)
                #pragma unroll
                for (int nj = 0; nj < 4; nj++) {
                    mma16816(acc[mi][2 * nj],     a[mi], bfr[nj][0], bfr[nj][2]);
                    mma16816(acc[mi][2 * nj + 1], a[mi], bfr[nj][1], bfr[nj][3]);
                }
        }
        __syncthreads();
    }
}

// Epilogue index helpers: for frag (mi, ni), lane l:
//   rows: rowBase + wm*32 + mi*16 + (l>>2) and +8
//   cols: colBase + wn*64 + ni*8 + (l&3)*2
// ---------------------------------------------------------------------------
// Stage 1: QKV projections. grid (8, 64, 3)
// ---------------------------------------------------------------------------
__global__ void __launch_bounds__(256) qkv_gemm(
    const float* __restrict__ bq, const float* __restrict__ bk,
    const float* __restrict__ bv)
{
    __shared__ SmemGemm sm;
    const int tid = threadIdx.x, lane = tid & 31, wid = tid >> 5;
    const int wm = wid & 3, wn = wid >> 2;
    const int z = blockIdx.z;
    const int rowBase = blockIdx.y * 128, colBase = blockIdx.x * 128;

    const bf16* Bh = g_Wh + (size_t)z * EE * EE;
    const bf16* Bl = g_Wl + (size_t)z * EE * EE;
    const float* bias = (z == 0) ? bq : (z == 1) ? bk : bv;
    bf16* oh = (z == 0) ? g_qh : (z == 1) ? g_kh : g_vh;
    bf16* ol = (z == 0) ? g_ql : (z == 1) ? g_kl : g_vl;
    const float alpha = (z == 0) ? 0.03125f : 1.0f;

    float acc[2][8][4] = {};
    gemm_mainloop(g_xh, g_xl, EE, Bh, Bl, EE, EE, rowBase, colBase, &sm, acc);

    #pragma unroll
    for (int mi = 0; mi < 2; mi++)
        #pragma unroll
        for (int ni = 0; ni < 8; ni++) {
            int col = colBase + wn * 64 + ni * 8 + (lane & 3) * 2;
            float b0 = bias[col], b1 = bias[col + 1];
            #pragma unroll
            for (int h = 0; h < 2; h++) {
                int row = rowBase + wm * 32 + mi * 16 + (lane >> 2) + h * 8;
                float y0 = (acc[mi][ni][2 * h]     + b0) * alpha;
                float y1 = (acc[mi][ni][2 * h + 1] + b1) * alpha;
                bf16 h0 = __float2bfloat16(y0), h1 = __float2bfloat16(y1);
                bf16 l0 = __float2bfloat16(y0 - __bfloat162float(h0));
                bf16 l1 = __float2bfloat16(y1 - __bfloat162float(h1));
                size_t off = (size_t)row * EE + col;
                *(__nv_bfloat162*)(oh + off) = __halves2bfloat162(h0, h1);
                *(__nv_bfloat162*)(ol + off) = __halves2bfloat162(l0, l1);
            }
        }
}

// ---------------------------------------------------------------------------
// Stage 2: scores = q_scaled @ k^T (causal block skip). grid (16, 16, 4)
// ---------------------------------------------------------------------------
__global__ void __launch_bounds__(256) scores_gemm()
{
    if (blockIdx.x > blockIdx.y) return;
    __shared__ SmemGemm sm;
    const int tid = threadIdx.x, lane = tid & 31, wid = tid >> 5;
    const int wm = wid & 3, wn = wid >> 2;
    const int z = blockIdx.z;
    const int rowBase = blockIdx.y * 128, colBase = blockIdx.x * 128;

    float acc[2][8][4] = {};
    gemm_mainloop(g_qh + (size_t)z * SS * EE, g_ql + (size_t)z * SS * EE, EE,
                  g_kh + (size_t)z * SS * EE, g_kl + (size_t)z * SS * EE, EE,
                  EE, rowBase, colBase, &sm, acc);

    float* out = g_sc + (size_t)z * SS * SS;
    #pragma unroll
    for (int mi = 0; mi < 2; mi++)
        #pragma unroll
        for (int ni = 0; ni < 8; ni++) {
            int col = colBase + wn * 64 + ni * 8 + (lane & 3) * 2;
            #pragma unroll
            for (int h = 0; h < 2; h++) {
                int row = rowBase + wm * 32 + mi * 16 + (lane >> 2) + h * 8;
                *(float2*)(out + (size_t)row * SS + col) =
                    make_float2(acc[mi][ni][2 * h], acc[mi][ni][2 * h + 1]);
            }
        }
}

// ---------------------------------------------------------------------------
// Stage 3: out = P @ v^T(transposed v) with causal K limit. grid (8, 16, 4)
// ---------------------------------------------------------------------------
__global__ void __launch_bounds__(256) av_gemm(float* __restrict__ gout)
{
    __shared__ SmemGemm sm;
    const int tid = threadIdx.x, lane = tid & 31, wid = tid >> 5;
    const int wm = wid & 3, wn = wid >> 2;
    const int z = blockIdx.z;
    const int rowBase = blockIdx.y * 128, colBase = blockIdx.x * 128;
    const int kEnd = (blockIdx.y + 1) * 128;

    float acc[2][8][4] = {};
    gemm_mainloop(g_ph + (size_t)z * SS * SS, g_pl + (size_t)z * SS * SS, SS,
                  g_vTh + (size_t)z * EE * SS, g_vTl + (size_t)z * EE * SS, SS,
                  kEnd, rowBase, colBase, &sm, acc);

    float* out = gout + (size_t)z * SS * EE;
    #pragma unroll
    for (int mi = 0; mi < 2; mi++)
        #pragma unroll
        for (int ni = 0; ni < 8; ni++) {
            int col = colBase + wn * 64 + ni * 8 + (lane & 3) * 2;
            #pragma unroll
            for (int h = 0; h < 2; h++) {
                int row = rowBase + wm * 32 + mi * 16 + (lane >> 2) + h * 8;
                *(float2*)(out + (size_t)row * EE + col) =
                    make_float2(acc[mi][ni][2 * h], acc[mi][ni][2 * h + 1]);
            }
        }
}

// ---------------------------------------------------------------------------
// Elementwise: fp32 -> bf16 hi/lo split
// ---------------------------------------------------------------------------
__global__ void split_kernel(const float* __restrict__ src,
                             bf16* __restrict__ h, bf16* __restrict__ l)
{
    size_t i = ((size_t)blockIdx.x * 256 + threadIdx.x) * 4;
    float4 v = *(const float4*)(src + i);
    bf16 h0 = __float2bfloat16(v.x), h1 = __float2bfloat16(v.y);
    bf16 h2 = __float2bfloat16(v.z), h3 = __float2bfloat16(v.w);
    bf16 l0 = __float2bfloat16(v.x - __bfloat162float(h0));
    bf16 l1 = __float2bfloat16(v.y - __bfloat162float(h1));
    bf16 l2 = __float2bfloat16(v.z - __bfloat162float(h2));
    bf16 l3 = __float2bfloat16(v.w - __bfloat162float(h3));
    *(__nv_bfloat162*)(h + i)     = __halves2bfloat162(h0, h1);
    *(__nv_bfloat162*)(h + i + 2) = __halves2bfloat162(h2, h3);
    *(__nv_bfloat162*)(l + i)     = __halves2bfloat162(l0, l1);
    *(__nv_bfloat162*)(l + i + 2) = __halves2bfloat162(l2, l3);
}

// ---------------------------------------------------------------------------
// Transpose v (per batch): [S, E] -> [E, S], hi and lo
// ---------------------------------------------------------------------------
__global__ void transpose_v()
{
    __shared__ bf16 th[32][33], tl[32][33];
    const int z = blockIdx.z;
    const int s0 = blockIdx.x * 32, e0 = blockIdx.y * 32;
    const int tx = threadIdx.x, ty = threadIdx.y;
    #pragma unroll
    for (int j = 0; j < 32; j += 8) {
        size_t src = ((size_t)z * SS + s0 + ty + j) * EE + e0 + tx;
        th[ty + j][tx] = g_vh[src];
        tl[ty + j][tx] = g_vl[src];
    }
    __syncthreads();
    #pragma unroll
    for (int j = 0; j < 32; j += 8) {
        size_t dst = ((size_t)z * EE + e0 + ty + j) * SS + s0 + tx;
        g_vTh[dst] = th[tx][ty + j];
        g_vTl[dst] = tl[tx][ty + j];
    }
}

// ---------------------------------------------------------------------------
// Causal softmax: fp32 scores -> bf16 hi/lo probabilities (tail zeroed)
// ---------------------------------------------------------------------------
__global__ void softmax_kernel()
{
    const int rowg = blockIdx.x;
    const int b = rowg >> 11;
    const int i = rowg & (SS - 1);
    const float* p = g_sc + (size_t)b * SS * SS + (size_t)i * SS;
    bf16* ph = g_ph + (size_t)b * SS * SS + (size_t)i * SS;
    bf16* pl = g_pl + (size_t)b * SS * SS + (size_t)i * SS;
    const int L = i + 1;
    const int kend = ((i >> 7) + 1) << 7;

    __shared__ float red[8], red2[8];
    const int t = threadIdx.x, lane = t & 31, w = t >> 5;

    float m = -1e30f;
    for (int j = t; j < L; j += 256) m = fmaxf(m, p[j]);
    #pragma unroll
    for (int o = 16; o; o >>= 1) m = fmaxf(m, __shfl_xor_sync(~0u, m, o));
    if (lane == 0) red[w] = m;
    __syncthreads();
    m = red[0];
    #pragma unroll
    for (int ww = 1; ww < 8; ww++) m = fmaxf(m, red[ww]);

    float s = 0.0f;
    for (int j = t; j < L; j += 256) s += __expf(p[j] - m);
    #pragma unroll
    for (int o = 16; o; o >>= 1) s += __shfl_xor_sync(~0u, s, o);
    if (lane == 0) red2[w] = s;
    __syncthreads();
    s = red2[0];
    #pragma unroll
    for (int ww = 1; ww < 8; ww++) s += red2[ww];

    const float inv = 1.0f / s;
    for (int j = t; j < L; j += 256) {
        float pv = __expf(p[j] - m) * inv;
        bf16 h = __float2bfloat16(pv);
        bf16 l = __float2bfloat16(pv - __bfloat162float(h));
        ph[j] = h;
        pl[j] = l;
    }
    const bf16 z0 = __float2bfloat16(0.0f);
    for (int j = L + t; j < kend; j += 256) { ph[j] = z0; pl[j] = z0; }
}

// ---------------------------------------------------------------------------
// Launch
// ---------------------------------------------------------------------------
extern "C" void kernel_launch(void* const* d_in, const int* in_sizes, int n_in,
                              void* d_out, int out_size)
{
    const float* x  = (const float*)d_in[0];
    const float* Wq = (const float*)d_in[2];
    const float* bq = (const float*)d_in[3];
    const float* Wk = (const float*)d_in[4];
    const float* bk = (const float*)d_in[5];
    const float* Wv = (const float*)d_in[6];
    const float* bv = (const float*)d_in[7];
    float* out = (float*)d_out;

    bf16 *xh, *xl, *wh, *wl;
    cudaGetSymbolAddress((void**)&xh, g_xh);
    cudaGetSymbolAddress((void**)&xl, g_xl);
    cudaGetSymbolAddress((void**)&wh, g_Wh);
    cudaGetSymbolAddress((void**)&wl, g_Wl);

    // 1) hi/lo splits of x and the three weight matrices
    split_kernel<<<(BB * SS * EE) / 1024, 256>>>(x, xh, xl);
    split_kernel<<<(EE * EE) / 1024, 256>>>(Wq, wh,                       wl);
    split_kernel<<<(EE * EE) / 1024, 256>>>(Wk, wh + (size_t)EE * EE,     wl + (size_t)EE * EE);
    split_kernel<<<(EE * EE) / 1024, 256>>>(Wv, wh + 2 * (size_t)EE * EE, wl + 2 * (size_t)EE * EE);

    // 2) QKV projections (q pre-scaled by 1/32)
    qkv_gemm<<<dim3(EE / 128, (BB * SS) / 128, 3), 256>>>(bq, bk, bv);

    // 3) transpose v for NT layout in AV
    transpose_v<<<dim3(SS / 32, EE / 32, BB), dim3(32, 8)>>>();

    // 4) scores = q_scaled @ k^T (lower-triangular blocks only)
    scores_gemm<<<dim3(SS / 128, SS / 128, BB), 256>>>();

    // 5) causal softmax -> bf16 hi/lo probabilities
    softmax_kernel<<<BB * SS, 256>>>();

    // 6) out = P @ v with causal K limit
    av_gemm<<<dim3(EE / 128, SS / 128, BB), 256>>>(out);
}

// round 4
// speedup vs baseline: 2.2489x; 1.1392x over previous
#include <cuda_runtime.h>
#include <cuda_bf16.h>

#define BB 4
#define SS 2048
#define EE 1024

typedef __nv_bfloat16 bf16;

// ---------------------------------------------------------------------------
// Scratch (device globals — no allocation allowed)
// ---------------------------------------------------------------------------
__device__ float g_sc[(size_t)BB * SS * SS];
__device__ float g_m[BB * SS], g_inv[BB * SS];
__device__ bf16 g_xh[(size_t)BB * SS * EE], g_xl[(size_t)BB * SS * EE];
__device__ bf16 g_Wh[3 * (size_t)EE * EE], g_Wl[3 * (size_t)EE * EE];
__device__ bf16 g_qh[(size_t)BB * SS * EE], g_ql[(size_t)BB * SS * EE];
__device__ bf16 g_kh[(size_t)BB * SS * EE], g_kl[(size_t)BB * SS * EE];
__device__ bf16 g_vh[(size_t)BB * SS * EE], g_vl[(size_t)BB * SS * EE];
__device__ bf16 g_vTh[(size_t)BB * EE * SS], g_vTl[(size_t)BB * EE * SS];

// ---------------------------------------------------------------------------
// PTX helpers (baseline sm_80+ features only — plain sm_103 target)
// ---------------------------------------------------------------------------
__device__ __forceinline__ unsigned smem_u32(const void* p) {
    unsigned a;
    asm("{ .reg .u64 t; cvta.to.shared.u64 t, %1; cvt.u32.u64 %0, t; }"
        : "=r"(a) : "l"(p));
    return a;
}
__device__ __forceinline__ void cp16(unsigned dst, const void* src) {
    asm volatile("cp.async.cg.shared.global [%0], [%1], 16;"
                 :: "r"(dst), "l"(src) : "memory");
}
__device__ __forceinline__ void cp_commit() {
    asm volatile("cp.async.commit_group;" ::: "memory");
}
__device__ __forceinline__ void cp_wait1() {
    asm volatile("cp.async.wait_group 1;" ::: "memory");
}
__device__ __forceinline__ void cp_wait0() {
    asm volatile("cp.async.wait_group 0;" ::: "memory");
}
__device__ __forceinline__ void ldsm4(unsigned& r0, unsigned& r1, unsigned& r2,
                                      unsigned& r3, unsigned addr) {
    asm volatile("ldmatrix.sync.aligned.m8n8.x4.shared.b16 {%0,%1,%2,%3}, [%4];"
                 : "=r"(r0), "=r"(r1), "=r"(r2), "=r"(r3) : "r"(addr));
}
__device__ __forceinline__ void mma16816(float* d, const unsigned* a,
                                         unsigned b0, unsigned b1) {
    asm volatile(
        "mma.sync.aligned.m16n8k16.row.col.f32.bf16.bf16.f32 "
        "{%0,%1,%2,%3}, {%4,%5,%6,%7}, {%8,%9}, {%0,%1,%2,%3};"
        : "+f"(d[0]), "+f"(d[1]), "+f"(d[2]), "+f"(d[3])
        : "r"(a[0]), "r"(a[1]), "r"(a[2]), "r"(a[3]), "r"(b0), "r"(b1));
}

// ---------------------------------------------------------------------------
// Tile layout: per buffer 4 tiles [Ah, Al, Bh, Bl], each 128 rows x 32 bf16
// (rows padded to 40 bf16 = 80B, 16B-aligned for ldmatrix)
// ---------------------------------------------------------------------------
#define ROWPAD 40
#define ROWB   (ROWPAD * 2)
#define TILE_B (128 * ROWB)                 // 10240 bytes
#define SMEM_BYTES (2 * 4 * TILE_B)         // 81920 bytes

// 3-pass compute on one buffered k-tile: acc += Ah*Bh + Al*Bh + Ah*Bl
__device__ __forceinline__ void compute_tiles(unsigned smBase, int buf,
                                              int wm, int wn, int lrow, int lk,
                                              float acc[2][8][4])
{
    const unsigned tb = smBase + buf * (4 * TILE_B);
    #pragma unroll
    for (int ks = 0; ks < 2; ks++) {
        unsigned ah[2][4], al[2][4], bh[4][4], bl[4][4];
        #pragma unroll
        for (int mi = 0; mi < 2; mi++) {
            unsigned off = (wm * 32 + mi * 16 + lrow) * ROWB + ks * 32 + lk;
            ldsm4(ah[mi][0], ah[mi][1], ah[mi][2], ah[mi][3], tb + 0 * TILE_B + off);
            ldsm4(al[mi][0], al[mi][1], al[mi][2], al[mi][3], tb + 1 * TILE_B + off);
        }
        #pragma unroll
        for (int nj = 0; nj < 4; nj++) {
            unsigned off = (wn * 64 + nj * 16 + lrow) * ROWB + ks * 32 + lk;
            ldsm4(bh[nj][0], bh[nj][1], bh[nj][2], bh[nj][3], tb + 2 * TILE_B + off);
            ldsm4(bl[nj][0], bl[nj][1], bl[nj][2], bl[nj][3], tb + 3 * TILE_B + off);
        }
        #pragma unroll
        for (int mi = 0; mi < 2; mi++)
            #pragma unroll
            for (int nj = 0; nj < 4; nj++) {
                mma16816(acc[mi][2 * nj],     ah[mi], bh[nj][0], bh[nj][2]);
                mma16816(acc[mi][2 * nj + 1], ah[mi], bh[nj][1], bh[nj][3]);
                mma16816(acc[mi][2 * nj],     al[mi], bh[nj][0], bh[nj][2]);
                mma16816(acc[mi][2 * nj + 1], al[mi], bh[nj][1], bh[nj][3]);
                mma16816(acc[mi][2 * nj],     ah[mi], bl[nj][0], bl[nj][2]);
                mma16816(acc[mi][2 * nj + 1], ah[mi], bl[nj][1], bl[nj][3]);
            }
    }
}

// cp.async loader for all 4 bf16 tiles
__device__ __forceinline__ void load_tiles4(unsigned smBase, int buf,
    const bf16* Ah, const bf16* Al, int lda,
    const bf16* Bh, const bf16* Bl, int ldb,
    int rowBase, int colBase, int kt, int tid)
{
    const unsigned dstb = smBase + buf * (4 * TILE_B);
    const char* srcA_h = (const char*)(Ah + (size_t)rowBase * lda + kt);
    const char* srcA_l = (const char*)(Al + (size_t)rowBase * lda + kt);
    const char* srcB_h = (const char*)(Bh + (size_t)colBase * ldb + kt);
    const char* srcB_l = (const char*)(Bl + (size_t)colBase * ldb + kt);
    const size_t strA = (size_t)lda * 2, strB = (size_t)ldb * 2;
    #pragma unroll
    for (int i = 0; i < 8; i++) {
        const int tile = i >> 1;                       // compile-time
        int within = tid + (i & 1) * 256;
        int row = within >> 2, c = (within & 3) * 16;
        const char* src = (tile == 0) ? srcA_h + row * strA + c
                        : (tile == 1) ? srcA_l + row * strA + c
                        : (tile == 2) ? srcB_h + row * strB + c
                                      : srcB_l + row * strB + c;
        cp16(dstb + tile * TILE_B + row * ROWB + c, src);
    }
}

// Full bf16 GEMM mainloop (qkv + scores)
__device__ __forceinline__ void gemm_mainloop(
    const bf16* __restrict__ Ah, const bf16* __restrict__ Al, int lda,
    const bf16* __restrict__ Bh, const bf16* __restrict__ Bl, int ldb,
    int kEnd, int rowBase, int colBase, unsigned smBase, float acc[2][8][4])
{
    const int tid = threadIdx.x;
    const int lane = tid & 31, wid = tid >> 5;
    const int wm = wid & 3, wn = wid >> 2;
    const int lrow = lane & 15, lk = (lane >> 4) * 16;
    const int kTiles = kEnd >> 5;

    load_tiles4(smBase, 0, Ah, Al, lda, Bh, Bl, ldb, rowBase, colBase, 0, tid);
    cp_commit();

    for (int it = 0; it < kTiles; ++it) {
        if (it + 1 < kTiles) {
            load_tiles4(smBase, (it + 1) & 1, Ah, Al, lda, Bh, Bl, ldb,
                        rowBase, colBase, (it + 1) << 5, tid);
            cp_commit();
            cp_wait1();
        } else {
            cp_wait0();
        }
        __syncthreads();
        compute_tiles(smBase, it & 1, wm, wn, lrow, lk, acc);
        __syncthreads();
    }
}

// ---------------------------------------------------------------------------
// Stage 1: QKV projections. grid (8, 64, 3)
// ---------------------------------------------------------------------------
__global__ void __launch_bounds__(256) qkv_gemm(
    const float* __restrict__ bq, const float* __restrict__ bk,
    const float* __restrict__ bv)
{
    extern __shared__ char smc[];
    unsigned smBase = smem_u32(smc);
    const int tid = threadIdx.x, lane = tid & 31, wid = tid >> 5;
    const int wm = wid & 3, wn = wid >> 2;
    const int z = blockIdx.z;
    const int rowBase = blockIdx.y * 128, colBase = blockIdx.x * 128;

    const bf16* Bh = g_Wh + (size_t)z * EE * EE;
    const bf16* Bl = g_Wl + (size_t)z * EE * EE;
    const float* bias = (z == 0) ? bq : (z == 1) ? bk : bv;
    bf16* oh = (z == 0) ? g_qh : (z == 1) ? g_kh : g_vh;
    bf16* ol = (z == 0) ? g_ql : (z == 1) ? g_kl : g_vl;
    const float alpha = (z == 0) ? 0.03125f : 1.0f;

    float acc[2][8][4] = {};
    gemm_mainloop(g_xh, g_xl, EE, Bh, Bl, EE, EE, rowBase, colBase, smBase, acc);

    #pragma unroll
    for (int mi = 0; mi < 2; mi++)
        #pragma unroll
        for (int ni = 0; ni < 8; ni++) {
            int col = colBase + wn * 64 + ni * 8 + (lane & 3) * 2;
            float b0 = bias[col], b1 = bias[col + 1];
            #pragma unroll
            for (int h = 0; h < 2; h++) {
                int row = rowBase + wm * 32 + mi * 16 + (lane >> 2) + h * 8;
                float y0 = (acc[mi][ni][2 * h]     + b0) * alpha;
                float y1 = (acc[mi][ni][2 * h + 1] + b1) * alpha;
                bf16 h0 = __float2bfloat16(y0), h1 = __float2bfloat16(y1);
                bf16 l0 = __float2bfloat16(y0 - __bfloat162float(h0));
                bf16 l1 = __float2bfloat16(y1 - __bfloat162float(h1));
                size_t off = (size_t)row * EE + col;
                *(__nv_bfloat162*)(oh + off) = __halves2bfloat162(h0, h1);
                *(__nv_bfloat162*)(ol + off) = __halves2bfloat162(l0, l1);
            }
        }
}

// ---------------------------------------------------------------------------
// Stage 2: scores = q_scaled @ k^T (causal block skip). grid (16, 16, 4)
// ---------------------------------------------------------------------------
__global__ void __launch_bounds__(256) scores_gemm()
{
    if (blockIdx.x > blockIdx.y) return;
    extern __shared__ char smc[];
    unsigned smBase = smem_u32(smc);
    const int tid = threadIdx.x, lane = tid & 31, wid = tid >> 5;
    const int wm = wid & 3, wn = wid >> 2;
    const int z = blockIdx.z;
    const int rowBase = blockIdx.y * 128, colBase = blockIdx.x * 128;

    float acc[2][8][4] = {};
    gemm_mainloop(g_qh + (size_t)z * SS * EE, g_ql + (size_t)z * SS * EE, EE,
                  g_kh + (size_t)z * SS * EE, g_kl + (size_t)z * SS * EE, EE,
                  EE, rowBase, colBase, smBase, acc);

    float* out = g_sc + (size_t)z * SS * SS;
    #pragma unroll
    for (int mi = 0; mi < 2; mi++)
        #pragma unroll
        for (int ni = 0; ni < 8; ni++) {
            int col = colBase + wn * 64 + ni * 8 + (lane & 3) * 2;
            #pragma unroll
            for (int h = 0; h < 2; h++) {
                int row = rowBase + wm * 32 + mi * 16 + (lane >> 2) + h * 8;
                *(float2*)(out + (size_t)row * SS + col) =
                    make_float2(acc[mi][ni][2 * h], acc[mi][ni][2 * h + 1]);
            }
        }
}

// ---------------------------------------------------------------------------
// Stage 2b: per-row softmax stats (max, 1/sumexp). grid B*S
// ---------------------------------------------------------------------------
__global__ void stats_kernel()
{
    const int rowg = blockIdx.x;
    const int b = rowg >> 11;
    const int i = rowg & (SS - 1);
    const float* p = g_sc + (size_t)b * SS * SS + (size_t)i * SS;
    const int L = i + 1;

    __shared__ float red[8], red2[8];
    const int t = threadIdx.x, lane = t & 31, w = t >> 5;

    float m = -1e30f;
    for (int j = t; j < L; j += 256) m = fmaxf(m, p[j]);
    #pragma unroll
    for (int o = 16; o; o >>= 1) m = fmaxf(m, __shfl_xor_sync(~0u, m, o));
    if (lane == 0) red[w] = m;
    __syncthreads();
    m = red[0];
    #pragma unroll
    for (int ww = 1; ww < 8; ww++) m = fmaxf(m, red[ww]);

    float s = 0.0f;
    for (int j = t; j < L; j += 256) s += __expf(p[j] - m);
    #pragma unroll
    for (int o = 16; o; o >>= 1) s += __shfl_xor_sync(~0u, s, o);
    if (lane == 0) red2[w] = s;
    __syncthreads();
    s = red2[0];
    #pragma unroll
    for (int ww = 1; ww < 8; ww++) s += red2[ww];

    if (t == 0) {
        g_m[rowg] = m;
        g_inv[rowg] = 1.0f / s;
    }
}

// ---------------------------------------------------------------------------
// Stage 3: out = P @ vT with fused softmax. grid (8, 16, 4)
// A tiles built in-register from fp32 scores: p = exp(s-m)*inv (causal mask),
// split to bf16 hi/lo, STS. B (vT hi/lo) via cp.async.
// ---------------------------------------------------------------------------
__global__ void __launch_bounds__(256) av_gemm(float* __restrict__ gout)
{
    extern __shared__ char smc[];
    unsigned smBase = smem_u32(smc);
    const int tid = threadIdx.x, lane = tid & 31, wid = tid >> 5;
    const int wm = wid & 3, wn = wid >> 2;
    const int lrow = lane & 15, lk = (lane >> 4) * 16;
    const int z = blockIdx.z;
    const int rowBase = blockIdx.y * 128, colBase = blockIdx.x * 128;
    const int kTiles = (blockIdx.y + 1) * 4;   // kEnd/32

    const bf16* Bh = g_vTh + (size_t)z * EE * SS;
    const bf16* Bl = g_vTl + (size_t)z * EE * SS;
    const float* sc = g_sc + (size_t)z * SS * SS;

    // Per-thread fixed score row: r = tid>>1, 16 cols at (tid&1)*16
    const int r = tid >> 1, ch = (tid & 1) * 16;
    const int grow = rowBase + r;
    const float rm = g_m[z * SS + grow];
    const float rinv = g_inv[z * SS + grow];
    const float* srow = sc + (size_t)grow * SS + ch;

    // --- helpers (lambdas) ---
    auto load_B = [&](int buf, int kt) {
        const unsigned dstb = smBase + buf * (4 * TILE_B);
        const char* sBh = (const char*)(Bh + (size_t)colBase * SS + kt);
        const char* sBl = (const char*)(Bl + (size_t)colBase * SS + kt);
        const size_t str = (size_t)SS * 2;
        #pragma unroll
        for (int i = 0; i < 4; i++) {
            const int tile = 2 + (i >> 1);
            int within = tid + (i & 1) * 256;
            int row = within >> 2, c = (within & 3) * 16;
            const char* src = (tile == 2) ? sBh + row * str + c : sBl + row * str + c;
            cp16(dstb + tile * TILE_B + row * ROWB + c, src);
        }
    };
    float4 sreg[4];
    auto ldg_A = [&](int kt) {
        const float* s0 = srow + kt;
        #pragma unroll
        for (int j = 0; j < 4; j++) sreg[j] = *(const float4*)(s0 + j * 4);
    };
    auto sts_A = [&](int buf, int kt) {
        const unsigned dstb = smBase + buf * (4 * TILE_B);
        char* base = smc + (dstb - smBase);
        #pragma unroll
        for (int j = 0; j < 4; j++) {
            float sv[4] = {sreg[j].x, sreg[j].y, sreg[j].z, sreg[j].w};
            float pv[4];
            #pragma unroll
            for (int e = 0; e < 4; e++) {
                int gcol = kt + ch + j * 4 + e;
                pv[e] = (gcol <= grow) ? __expf(sv[e] - rm) * rinv : 0.0f;
            }
            bf16 h0 = __float2bfloat16(pv[0]), h1 = __float2bfloat16(pv[1]);
            bf16 h2 = __float2bfloat16(pv[2]), h3 = __float2bfloat16(pv[3]);
            bf16 l0 = __float2bfloat16(pv[0] - __bfloat162float(h0));
            bf16 l1 = __float2bfloat16(pv[1] - __bfloat162float(h1));
            bf16 l2 = __float2bfloat16(pv[2] - __bfloat162float(h2));
            bf16 l3 = __float2bfloat16(pv[3] - __bfloat162float(h3));
            int boff = r * ROWB + (ch + j * 4) * 2;
            *(__nv_bfloat162*)(base + 0 * TILE_B + boff)     = __halves2bfloat162(h0, h1);
            *(__nv_bfloat162*)(base + 0 * TILE_B + boff + 4) = __halves2bfloat162(h2, h3);
            *(__nv_bfloat162*)(base + 1 * TILE_B + boff)     = __halves2bfloat162(l0, l1);
            *(__nv_bfloat162*)(base + 1 * TILE_B + boff + 4) = __halves2bfloat162(l2, l3);
        }
    };

    float acc[2][8][4] = {};

    // prologue: stage 0
    load_B(0, 0);
    cp_commit();
    ldg_A(0);
    sts_A(0, 0);

    for (int it = 0; it < kTiles; ++it) {
        const bool more = (it + 1 < kTiles);
        if (more) {
            load_B((it + 1) & 1, (it + 1) << 5);
            cp_commit();
            ldg_A((it + 1) << 5);
            cp_wait1();
        } else {
            cp_wait0();
        }
        __syncthreads();
        compute_tiles(smBase, it & 1, wm, wn, lrow, lk, acc);
        if (more) sts_A((it + 1) & 1, (it + 1) << 5);
        __syncthreads();
    }

    float* out = gout + (size_t)z * SS * EE;
    #pragma unroll
    for (int mi = 0; mi < 2; mi++)
        #pragma unroll
        for (int ni = 0; ni < 8; ni++) {
            int col = colBase + wn * 64 + ni * 8 + (lane & 3) * 2;
            #pragma unroll
            for (int h = 0; h < 2; h++) {
                int row = rowBase + wm * 32 + mi * 16 + (lane >> 2) + h * 8;
                *(float2*)(out + (size_t)row * EE + col) =
                    make_float2(acc[mi][ni][2 * h], acc[mi][ni][2 * h + 1]);
            }
        }
}

// ---------------------------------------------------------------------------
// Elementwise: fp32 -> bf16 hi/lo split
// ---------------------------------------------------------------------------
__global__ void split_kernel(const float* __restrict__ src,
                             bf16* __restrict__ h, bf16* __restrict__ l)
{
    size_t i = ((size_t)blockIdx.x * 256 + threadIdx.x) * 4;
    float4 v = *(const float4*)(src + i);
    bf16 h0 = __float2bfloat16(v.x), h1 = __float2bfloat16(v.y);
    bf16 h2 = __float2bfloat16(v.z), h3 = __float2bfloat16(v.w);
    bf16 l0 = __float2bfloat16(v.x - __bfloat162float(h0));
    bf16 l1 = __float2bfloat16(v.y - __bfloat162float(h1));
    bf16 l2 = __float2bfloat16(v.z - __bfloat162float(h2));
    bf16 l3 = __float2bfloat16(v.w - __bfloat162float(h3));
    *(__nv_bfloat162*)(h + i)     = __halves2bfloat162(h0, h1);
    *(__nv_bfloat162*)(h + i + 2) = __halves2bfloat162(h2, h3);
    *(__nv_bfloat162*)(l + i)     = __halves2bfloat162(l0, l1);
    *(__nv_bfloat162*)(l + i + 2) = __halves2bfloat162(l2, l3);
}

// ---------------------------------------------------------------------------
// Transpose v (per batch): [S, E] -> [E, S], hi and lo
// ---------------------------------------------------------------------------
__global__ void transpose_v()
{
    __shared__ bf16 th[32][33], tl[32][33];
    const int z = blockIdx.z;
    const int s0 = blockIdx.x * 32, e0 = blockIdx.y * 32;
    const int tx = threadIdx.x, ty = threadIdx.y;
    #pragma unroll
    for (int j = 0; j < 32; j += 8) {
        size_t src = ((size_t)z * SS + s0 + ty + j) * EE + e0 + tx;
        th[ty + j][tx] = g_vh[src];
        tl[ty + j][tx] = g_vl[src];
    }
    __syncthreads();
    #pragma unroll
    for (int j = 0; j < 32; j += 8) {
        size_t dst = ((size_t)z * EE + e0 + ty + j) * SS + s0 + tx;
        g_vTh[dst] = th[tx][ty + j];
        g_vTl[dst] = tl[tx][ty + j];
    }
}

// ---------------------------------------------------------------------------
// Launch
// ---------------------------------------------------------------------------
extern "C" void kernel_launch(void* const* d_in, const int* in_sizes, int n_in,
                              void* d_out, int out_size)
{
    const float* x  = (const float*)d_in[0];
    const float* Wq = (const float*)d_in[2];
    const float* bq = (const float*)d_in[3];
    const float* Wk = (const float*)d_in[4];
    const float* bk = (const float*)d_in[5];
    const float* Wv = (const float*)d_in[6];
    const float* bv = (const float*)d_in[7];
    float* out = (float*)d_out;

    bf16 *xh, *xl, *wh, *wl;
    cudaGetSymbolAddress((void**)&xh, g_xh);
    cudaGetSymbolAddress((void**)&xl, g_xl);
    cudaGetSymbolAddress((void**)&wh, g_Wh);
    cudaGetSymbolAddress((void**)&wl, g_Wl);

    static bool attr_done = false;
    if (!attr_done) {
        cudaFuncSetAttribute(qkv_gemm,    cudaFuncAttributeMaxDynamicSharedMemorySize, SMEM_BYTES);
        cudaFuncSetAttribute(scores_gemm, cudaFuncAttributeMaxDynamicSharedMemorySize, SMEM_BYTES);
        cudaFuncSetAttribute(av_gemm,     cudaFuncAttributeMaxDynamicSharedMemorySize, SMEM_BYTES);
        attr_done = true;
    }

    // 1) hi/lo splits
    split_kernel<<<(BB * SS * EE) / 1024, 256>>>(x, xh, xl);
    split_kernel<<<(EE * EE) / 1024, 256>>>(Wq, wh,                       wl);
    split_kernel<<<(EE * EE) / 1024, 256>>>(Wk, wh + (size_t)EE * EE,     wl + (size_t)EE * EE);
    split_kernel<<<(EE * EE) / 1024, 256>>>(Wv, wh + 2 * (size_t)EE * EE, wl + 2 * (size_t)EE * EE);

    // 2) QKV projections (q pre-scaled by 1/32)
    qkv_gemm<<<dim3(EE / 128, (BB * SS) / 128, 3), 256, SMEM_BYTES>>>(bq, bk, bv);

    // 3) transpose v
    transpose_v<<<dim3(SS / 32, EE / 32, BB), dim3(32, 8)>>>();

    // 4) scores (lower-triangular blocks)
    scores_gemm<<<dim3(SS / 128, SS / 128, BB), 256, SMEM_BYTES>>>();

    // 5) per-row softmax stats
    stats_kernel<<<BB * SS, 256>>>();

    // 6) fused softmax + P @ vT
    av_gemm<<<dim3(EE / 128, SS / 128, BB), 256, SMEM_BYTES>>>(out);
}